// round 16
// baseline (speedup 1.0000x reference)
#include <cuda_runtime.h>

#define BATCH 8
#define INPUT_SIZE 8192
#define HIDDEN_SIZE 8192
#define OUTPUT_SIZE 2048
#define KDIM 16384

typedef unsigned long long u64;

#define NBLOCKS 296                      // 2 x 148 SMs, exact residency

// ---- Phase A (i2h): 8 K-slices x 37 blocks --------------------------------
#define NSLICE1 8
#define KSLICE1 (KDIM / NSLICE1)        // 2048
#define KS1_16B (KSLICE1 / 4)           // 512 x 16B per batch
#define BLKS_PER_SLICE1 37
#define R1 4
#define TILE_ROWS_1 (R1 * 8)            // 32
#define NTILES1 (HIDDEN_SIZE / TILE_ROWS_1)   // 256

// ---- Phase C (h2o): 64 row tiles x 4 K-splits = 256 units -----------------
#define R2 4
#define TILE_ROWS_2 (R2 * 8)            // 32
#define NTILES2 (OUTPUT_SIZE / TILE_ROWS_2)   // 64
#define NSPLIT2 4
#define KQ (HIDDEN_SIZE / NSPLIT2)      // 2048
#define TK  1024
#define TK16 (TK / 4)                   // 256 x 16B per batch per chunk

// Scratch (allocation-free)
__device__ float g_p1[NSLICE1][BATCH][HIDDEN_SIZE];   // 2 MB
__device__ float g_hidden[BATCH * HIDDEN_SIZE];       // 256 KB
__device__ float g_p2[NSPLIT2][BATCH][OUTPUT_SIZE];   // 256 KB

// Grid barrier state (generation counter: no reset needed across replays)
__device__ unsigned g_bar = 0;
__device__ volatile unsigned g_gen = 0;

__device__ __forceinline__ void grid_sync() {
    __syncthreads();
    if (threadIdx.x == 0) {
        unsigned gen = g_gen;
        __threadfence();
        if (atomicAdd(&g_bar, 1u) == NBLOCKS - 1u) {
            g_bar = 0;
            __threadfence();
            g_gen = gen + 1u;
        } else {
            while (g_gen == gen) __nanosleep(40);
        }
        __threadfence();
    }
    __syncthreads();
}

// ---------------------------------------------------------------------------
__device__ __forceinline__ void cp_async16(void* smem_dst, const void* gmem_src) {
    unsigned s = (unsigned)__cvta_generic_to_shared(smem_dst);
    asm volatile("cp.async.cg.shared.global [%0], [%1], 16;\n" :: "r"(s), "l"(gmem_src));
}
__device__ __forceinline__ void cp_commit()  { asm volatile("cp.async.commit_group;\n"); }
__device__ __forceinline__ void cp_wait1()   { asm volatile("cp.async.wait_group 1;\n"); }
__device__ __forceinline__ void cp_wait0()   { asm volatile("cp.async.wait_group 0;\n"); }

// Packed dual-FMA (non-volatile, reorderable); operands are native
// ulonglong2 halves from LDG.128/LDS.128 — zero packing cost.
__device__ __forceinline__ void fma2(u64& d, u64 a, u64 b) {
    asm("fma.rn.f32x2 %0, %1, %2, %0;" : "+l"(d) : "l"(a), "l"(b));
}
__device__ __forceinline__ float pair_sum(u64 v) {
    return __uint_as_float((unsigned)v) + __uint_as_float((unsigned)(v >> 32));
}

// ===========================================================================
// ONE persistent kernel: A=i2h partials, B=tanh-reduce, C=h2o partials,
// D=final reduce. grid=296 (exact 2/SM residency -> spin barrier is safe).
// ===========================================================================
__global__ __launch_bounds__(256, 2)
void rnn_fused_kernel(const float* __restrict__ x,
                      const float* __restrict__ h0,
                      const float* __restrict__ W,      // [HIDDEN, KDIM]
                      const float* __restrict__ bias1,
                      const float* __restrict__ W2,     // [OUT, HIDDEN]
                      const float* __restrict__ bias2,
                      float* __restrict__ out)
{
    extern __shared__ ulonglong2 smem[];   // 64 KB, reinterpreted per phase

    const int tid  = threadIdx.x;
    const int lane = tid & 31;
    const int warp = tid >> 5;
    const int bid  = blockIdx.x;

    // ======================= Phase A: i2h partials ========================
    {
        const int slice = bid / BLKS_PER_SLICE1;   // 0..7
        const int local = bid % BLKS_PER_SLICE1;   // 0..36

        const float* in = (slice < NSLICE1 / 2)
                            ? (x  + slice * KSLICE1)
                            : (h0 + slice * KSLICE1 - INPUT_SIZE);
        #pragma unroll
        for (int t = 0; t < 16; ++t) {
            int f  = tid + t * 256;
            int b  = f >> 9;                   // / KS1_16B
            int k4 = f & (KS1_16B - 1);
            smem[b * KS1_16B + k4] =
                ((const ulonglong2*)(in + (size_t)b * INPUT_SIZE))[k4];
        }
        __syncthreads();

        const size_t koff = (size_t)slice * KSLICE1;

        for (int tile = local; tile < NTILES1; tile += BLKS_PER_SLICE1) {
            const int row0 = tile * TILE_ROWS_1 + warp * R1;

            u64 acc[R1][BATCH];
            #pragma unroll
            for (int r = 0; r < R1; r++)
                #pragma unroll
                for (int b = 0; b < BATCH; b++)
                    acc[r][b] = 0ull;

            const ulonglong2* Wc0 = (const ulonglong2*)(W + (size_t)(row0 + 0) * KDIM + koff);
            const ulonglong2* Wc1 = (const ulonglong2*)(W + (size_t)(row0 + 1) * KDIM + koff);
            const ulonglong2* Wc2 = (const ulonglong2*)(W + (size_t)(row0 + 2) * KDIM + koff);
            const ulonglong2* Wc3 = (const ulonglong2*)(W + (size_t)(row0 + 3) * KDIM + koff);

            #pragma unroll
            for (int i = 0; i < KS1_16B / 32; ++i) {      // 16 strips
                const int k4 = i * 32 + lane;
                ulonglong2 w0 = __ldcs(Wc0 + k4);
                ulonglong2 w1 = __ldcs(Wc1 + k4);
                ulonglong2 w2 = __ldcs(Wc2 + k4);
                ulonglong2 w3 = __ldcs(Wc3 + k4);

                #pragma unroll
                for (int b = 0; b < BATCH; b++) {
                    ulonglong2 v = smem[b * KS1_16B + k4];
                    fma2(acc[0][b], w0.x, v.x);
                    fma2(acc[0][b], w0.y, v.y);
                    fma2(acc[1][b], w1.x, v.x);
                    fma2(acc[1][b], w1.y, v.y);
                    fma2(acc[2][b], w2.x, v.x);
                    fma2(acc[2][b], w2.y, v.y);
                    fma2(acc[3][b], w3.x, v.x);
                    fma2(acc[3][b], w3.y, v.y);
                }
            }

            #pragma unroll
            for (int r = 0; r < R1; r++) {
                #pragma unroll
                for (int b = 0; b < BATCH; b++) {
                    float s = pair_sum(acc[r][b]);
                    #pragma unroll
                    for (int off = 16; off > 0; off >>= 1)
                        s += __shfl_xor_sync(0xffffffffu, s, off);
                    if (lane == b)
                        g_p1[slice][b][row0 + r] = s;
                }
            }
        }
    }

    grid_sync();

    // ======================= Phase B: hidden = tanh(sum p1 + b1) ==========
    {
        const int total = BATCH * HIDDEN_SIZE / 4;     // 16384 float4
        for (int idx = bid * 256 + tid; idx < total; idx += NBLOCKS * 256) {
            int b  = idx >> 11;                         // / (HIDDEN/4)
            int h4 = idx & (HIDDEN_SIZE / 4 - 1);
            float4 a = __ldg((const float4*)bias1 + h4);
            #pragma unroll
            for (int s = 0; s < NSLICE1; s++) {
                float4 p = ((const float4*)&g_p1[s][b][0])[h4];
                a.x += p.x; a.y += p.y; a.z += p.z; a.w += p.w;
            }
            float4 r = make_float4(tanhf(a.x), tanhf(a.y), tanhf(a.z), tanhf(a.w));
            ((float4*)(g_hidden + b * HIDDEN_SIZE))[h4] = r;
        }
    }

    grid_sync();

    // ======================= Phase C: h2o partials ========================
    if (bid < NTILES2 * NSPLIT2) {                      // 256 active blocks
        const int tile  = bid & (NTILES2 - 1);
        const int split = bid >> 6;
        const int row0  = tile * TILE_ROWS_2 + warp * R2;
        const int kbase = split * KQ;
        const int NCHUNK = KQ / TK;   // 2

        // smem as double buffer: buf*2048 + b*TK16 + k4 (2 x 32 KB)
        u64 acc[R2][BATCH];
        #pragma unroll
        for (int r = 0; r < R2; r++)
            #pragma unroll
            for (int b = 0; b < BATCH; b++)
                acc[r][b] = 0ull;

        auto stage = [&](int c, int buf) {
            const float* src = g_hidden + kbase + c * TK;
            #pragma unroll
            for (int t = 0; t < 8; ++t) {
                int f  = tid + t * 256;
                int b  = f >> 8;               // / TK16
                int k4 = f & (TK16 - 1);
                cp_async16(&smem[buf * (BATCH * TK16) + b * TK16 + k4],
                           (const float4*)(src + (size_t)b * HIDDEN_SIZE) + k4);
            }
            cp_commit();
        };

        stage(0, 0);

        const ulonglong2* W0 = (const ulonglong2*)(W2 + (size_t)(row0 + 0) * HIDDEN_SIZE + kbase);
        const ulonglong2* W1 = (const ulonglong2*)(W2 + (size_t)(row0 + 1) * HIDDEN_SIZE + kbase);
        const ulonglong2* Wv = (const ulonglong2*)(W2 + (size_t)(row0 + 2) * HIDDEN_SIZE + kbase);
        const ulonglong2* W3 = (const ulonglong2*)(W2 + (size_t)(row0 + 3) * HIDDEN_SIZE + kbase);

        for (int c = 0; c < NCHUNK; ++c) {
            const int buf = c & 1;
            __syncthreads();
            if (c + 1 < NCHUNK) { stage(c + 1, buf ^ 1); cp_wait1(); }
            else                { cp_wait0(); }
            __syncthreads();

            const ulonglong2* Wc0 = W0 + c * TK16;
            const ulonglong2* Wc1 = W1 + c * TK16;
            const ulonglong2* Wc2 = Wv + c * TK16;
            const ulonglong2* Wc3 = W3 + c * TK16;
            const ulonglong2* sv  = &smem[buf * (BATCH * TK16)];

            #pragma unroll
            for (int i = 0; i < TK16 / 32; ++i) {         // 8 strips
                const int k4 = i * 32 + lane;
                ulonglong2 w0 = __ldcs(Wc0 + k4);
                ulonglong2 w1 = __ldcs(Wc1 + k4);
                ulonglong2 w2 = __ldcs(Wc2 + k4);
                ulonglong2 w3 = __ldcs(Wc3 + k4);

                #pragma unroll
                for (int b = 0; b < BATCH; b++) {
                    ulonglong2 v = sv[b * TK16 + k4];
                    fma2(acc[0][b], w0.x, v.x);
                    fma2(acc[0][b], w0.y, v.y);
                    fma2(acc[1][b], w1.x, v.x);
                    fma2(acc[1][b], w1.y, v.y);
                    fma2(acc[2][b], w2.x, v.x);
                    fma2(acc[2][b], w2.y, v.y);
                    fma2(acc[3][b], w3.x, v.x);
                    fma2(acc[3][b], w3.y, v.y);
                }
            }
        }

        #pragma unroll
        for (int r = 0; r < R2; r++) {
            #pragma unroll
            for (int b = 0; b < BATCH; b++) {
                float s = pair_sum(acc[r][b]);
                #pragma unroll
                for (int off = 16; off > 0; off >>= 1)
                    s += __shfl_xor_sync(0xffffffffu, s, off);
                if (lane == b)
                    g_p2[split][b][row0 + r] = s;
            }
        }
    }

    grid_sync();

    // ======================= Phase D: out = sum p2 + b2 ===================
    {
        const int total = BATCH * OUTPUT_SIZE / 4;     // 4096 float4
        for (int idx = bid * 256 + tid; idx < total; idx += NBLOCKS * 256) {
            int b  = idx >> 9;                          // / (OUT/4)
            int o4 = idx & (OUTPUT_SIZE / 4 - 1);
            float4 a = __ldg((const float4*)bias2 + o4);
            #pragma unroll
            for (int s = 0; s < NSPLIT2; s++) {
                float4 p = ((const float4*)&g_p2[s][b][0])[o4];
                a.x += p.x; a.y += p.y; a.z += p.z; a.w += p.w;
            }
            ((float4*)out)[idx] = a;
        }
    }
}

// ---------------------------------------------------------------------------
// Inputs: x, initial_hidden, i2h_weight, i2h_bias, h2o_weight, h2o_bias
// ---------------------------------------------------------------------------
extern "C" void kernel_launch(void* const* d_in, const int* in_sizes, int n_in,
                              void* d_out, int out_size) {
    const float* x  = (const float*)d_in[0];
    const float* h0 = (const float*)d_in[1];
    const float* W1 = (const float*)d_in[2];
    const float* b1 = (const float*)d_in[3];
    const float* W2 = (const float*)d_in[4];
    const float* b2 = (const float*)d_in[5];
    float* out      = (float*)d_out;

    const int SMEM = BATCH * KS1_16B * sizeof(ulonglong2);   // 64 KB dynamic
    cudaFuncSetAttribute(rnn_fused_kernel,
                         cudaFuncAttributeMaxDynamicSharedMemorySize, SMEM);

    rnn_fused_kernel<<<NBLOCKS, 256, SMEM>>>(x, h0, W1, b1, W2, b2, out);
}